// round 1
// baseline (speedup 1.0000x reference)
#include <cuda_runtime.h>
#include <cstdint>

// Problem constants (match reference)
#define S_NUM 2048
#define K_NEG 128
#define D_DIM 128
#define GAMMA 12.0f

// Output layout: for each part p in {0,1,2}:
//   pos  [S]      at p*PART_STRIDE
//   neg_t[S*K]    at p*PART_STRIDE + S
//   neg_h[S*K]    at p*PART_STRIDE + S + S*K
#define PART_STRIDE (S_NUM + 2 * S_NUM * K_NEG)   // 526336

__global__ __launch_bounds__(256, 8)
void sample_score_kernel(
    const float* __restrict__ emb,        // [N, D]
    const float* __restrict__ relG2,      // [R2, D]
    const float* __restrict__ relTT,      // [R1, D]
    const float* __restrict__ relTO,      // [D]
    const int* __restrict__ h1, const int* __restrict__ r1, const int* __restrict__ t1,
    const int* __restrict__ nt1, const int* __restrict__ nh1,
    const int* __restrict__ h2, const int* __restrict__ r2, const int* __restrict__ t2,
    const int* __restrict__ nt2, const int* __restrict__ nh2,
    const int* __restrict__ h3, const int* __restrict__ t3,
    const int* __restrict__ nt3, const int* __restrict__ nh3,
    float* __restrict__ out)
{
    const int s    = blockIdx.x;
    const int part = blockIdx.y;
    const int tid  = threadIdx.x;
    const int warp = tid >> 5;
    const int lane = tid & 31;

    __shared__ float s_hr[D_DIM];     // h + r
    __shared__ float s_rmt[D_DIM];    // r - t
    __shared__ float s_red[4];        // pos-score warp partials

    // Select per-part pointers
    const int *hp, *tp, *ntp, *nhp;
    const int* rp;               // relation index array (nullptr for part 2)
    const float* rel;
    if (part == 0)      { hp=h1; rp=r1;      tp=t1; ntp=nt1; nhp=nh1; rel=relG2; }
    else if (part == 1) { hp=h2; rp=r2;      tp=t2; ntp=nt2; nhp=nh2; rel=relTT; }
    else                { hp=h3; rp=nullptr; tp=t3; ntp=nt3; nhp=nh3; rel=relTO; }

    float* out_pos = out + (size_t)part * PART_STRIDE;
    float* out_nt  = out_pos + S_NUM;
    float* out_nh  = out_nt  + (size_t)S_NUM * K_NEG;

    // ---- Setup: load h, r, t rows; build hr / rmt in smem; start pos reduce ----
    if (tid < D_DIM) {
        const size_t hrow = (size_t)hp[s] * D_DIM;
        const size_t trow = (size_t)tp[s] * D_DIM;
        const float hv = __ldg(emb + hrow + tid);
        const float tv = __ldg(emb + trow + tid);
        float rv;
        if (rp) rv = __ldg(rel + (size_t)rp[s] * D_DIM + tid);
        else    rv = __ldg(rel + tid);

        s_hr[tid]  = hv + rv;
        s_rmt[tid] = rv - tv;

        // positive score partial: |h + r - t|
        float a = fabsf(hv + rv - tv);
        #pragma unroll
        for (int o = 16; o > 0; o >>= 1)
            a += __shfl_down_sync(0xffffffffu, a, o);
        if (lane == 0) s_red[warp] = a;
    }
    __syncthreads();
    if (tid == 0) {
        out_pos[s] = GAMMA - (s_red[0] + s_red[1] + s_red[2] + s_red[3]);
    }

    // Per-lane registers: 4 contiguous elements of hr / rmt (conflict-free LDS.128)
    const float4 hr  = reinterpret_cast<const float4*>(s_hr)[lane];
    const float4 rmt = reinterpret_cast<const float4*>(s_rmt)[lane];

    const int* nt_row = ntp + (size_t)s * K_NEG;
    const int* nh_row = nhp + (size_t)s * K_NEG;
    float* onT = out_nt + (size_t)s * K_NEG;
    float* onH = out_nh + (size_t)s * K_NEG;

    // ---- Main loop: each warp handles 2 tail + 2 head negatives per iter ----
    // 8 warps, K=128 -> j in {2w, 2w+1, 2w+16, ...}: 8 iterations, 4 gathers each.
    for (int j = warp * 2; j < K_NEG; j += 16) {
        const int ia = nt_row[j];
        const int ib = nt_row[j + 1];
        const int ic = nh_row[j];
        const int id = nh_row[j + 1];

        const float4 ta = reinterpret_cast<const float4*>(emb + (size_t)ia * D_DIM)[lane];
        const float4 tb = reinterpret_cast<const float4*>(emb + (size_t)ib * D_DIM)[lane];
        const float4 hc = reinterpret_cast<const float4*>(emb + (size_t)ic * D_DIM)[lane];
        const float4 hd = reinterpret_cast<const float4*>(emb + (size_t)id * D_DIM)[lane];

        float sa = fabsf(hr.x - ta.x) + fabsf(hr.y - ta.y)
                 + fabsf(hr.z - ta.z) + fabsf(hr.w - ta.w);
        float sb = fabsf(hr.x - tb.x) + fabsf(hr.y - tb.y)
                 + fabsf(hr.z - tb.z) + fabsf(hr.w - tb.w);
        float sc = fabsf(hc.x + rmt.x) + fabsf(hc.y + rmt.y)
                 + fabsf(hc.z + rmt.z) + fabsf(hc.w + rmt.w);
        float sd = fabsf(hd.x + rmt.x) + fabsf(hd.y + rmt.y)
                 + fabsf(hd.z + rmt.z) + fabsf(hd.w + rmt.w);

        #pragma unroll
        for (int o = 16; o > 0; o >>= 1) {
            sa += __shfl_down_sync(0xffffffffu, sa, o);
            sb += __shfl_down_sync(0xffffffffu, sb, o);
            sc += __shfl_down_sync(0xffffffffu, sc, o);
            sd += __shfl_down_sync(0xffffffffu, sd, o);
        }
        if (lane == 0) {
            onT[j]     = GAMMA - sa;
            onT[j + 1] = GAMMA - sb;
            onH[j]     = GAMMA - sc;
            onH[j + 1] = GAMMA - sd;
        }
    }
}

extern "C" void kernel_launch(void* const* d_in, const int* in_sizes, int n_in,
                              void* d_out, int out_size) {
    const float* emb   = (const float*)d_in[0];
    const float* relG2 = (const float*)d_in[1];
    const float* relTT = (const float*)d_in[2];
    const float* relTO = (const float*)d_in[3];
    const int* h1  = (const int*)d_in[4];
    const int* r1  = (const int*)d_in[5];
    const int* t1  = (const int*)d_in[6];
    const int* nt1 = (const int*)d_in[7];
    const int* nh1 = (const int*)d_in[8];
    const int* h2  = (const int*)d_in[9];
    const int* r2  = (const int*)d_in[10];
    const int* t2  = (const int*)d_in[11];
    const int* nt2 = (const int*)d_in[12];
    const int* nh2 = (const int*)d_in[13];
    const int* h3  = (const int*)d_in[14];
    const int* t3  = (const int*)d_in[15];
    const int* nt3 = (const int*)d_in[16];
    const int* nh3 = (const int*)d_in[17];

    dim3 grid(S_NUM, 3);
    sample_score_kernel<<<grid, 256>>>(
        emb, relG2, relTT, relTO,
        h1, r1, t1, nt1, nh1,
        h2, r2, t2, nt2, nh2,
        h3, t3, nt3, nh3,
        (float*)d_out);
}

// round 2
// speedup vs baseline: 1.0939x; 1.0939x over previous
#include <cuda_runtime.h>
#include <cstdint>

// Problem constants (match reference)
#define S_NUM 2048
#define K_NEG 128
#define D_DIM 128
#define GAMMA 12.0f

// Output layout: for each part p in {0,1,2}:
//   pos  [S]      at p*PART_STRIDE
//   neg_t[S*K]    at p*PART_STRIDE + S
//   neg_h[S*K]    at p*PART_STRIDE + S + S*K
#define PART_STRIDE (S_NUM + 2 * S_NUM * K_NEG)   // 526336

__device__ __forceinline__ float4 ld_row4(const float* __restrict__ emb, int idx, int lane) {
    return __ldg(reinterpret_cast<const float4*>(emb + (size_t)idx * D_DIM) + lane);
}

__global__ __launch_bounds__(256, 4)
void sample_score_kernel(
    const float* __restrict__ emb,        // [N, D]
    const float* __restrict__ relG2,      // [R2, D]
    const float* __restrict__ relTT,      // [R1, D]
    const float* __restrict__ relTO,      // [D]
    const int* __restrict__ h1, const int* __restrict__ r1, const int* __restrict__ t1,
    const int* __restrict__ nt1, const int* __restrict__ nh1,
    const int* __restrict__ h2, const int* __restrict__ r2, const int* __restrict__ t2,
    const int* __restrict__ nt2, const int* __restrict__ nh2,
    const int* __restrict__ h3, const int* __restrict__ t3,
    const int* __restrict__ nt3, const int* __restrict__ nh3,
    float* __restrict__ out)
{
    const int s    = blockIdx.x;
    const int part = blockIdx.y;
    const int warp = threadIdx.x >> 5;
    const int lane = threadIdx.x & 31;

    // Select per-part pointers
    const int *hp, *tp, *ntp, *nhp;
    const int* rp;               // relation index array (nullptr for part 2)
    const float* rel;
    if (part == 0)      { hp=h1; rp=r1;      tp=t1; ntp=nt1; nhp=nh1; rel=relG2; }
    else if (part == 1) { hp=h2; rp=r2;      tp=t2; ntp=nt2; nhp=nh2; rel=relTT; }
    else                { hp=h3; rp=nullptr; tp=t3; ntp=nt3; nhp=nh3; rel=relTO; }

    float* out_pos = out + (size_t)part * PART_STRIDE;
    float* out_nt  = out_pos + S_NUM;
    float* out_nh  = out_nt  + (size_t)S_NUM * K_NEG;

    const int* nt_row = ntp + (size_t)s * K_NEG;
    const int* nh_row = nhp + (size_t)s * K_NEG;
    const int  j0 = warp * 16;               // this warp's 16 tail- and 16 head-negatives

    // Lane-parallel index load: lanes 0-15 carry nt indices, 16-31 carry nh indices.
    const int myidx = (lane < 16) ? __ldcs(nt_row + j0 + lane)
                                  : __ldcs(nh_row + j0 + (lane & 15));

    const unsigned FULL = 0xffffffffu;

    // ---- Issue iteration-0 negative gathers FIRST (independent of h/r/t) ----
    {
        // handled below via the same prefetch pattern (i = -1 prologue)
    }
    int ia = __shfl_sync(FULL, myidx, 0);
    int ib = __shfl_sync(FULL, myidx, 1);
    int ic = __shfl_sync(FULL, myidx, 16);
    int id = __shfl_sync(FULL, myidx, 17);
    float4 cta = ld_row4(emb, ia, lane);
    float4 ctb = ld_row4(emb, ib, lane);
    float4 cha = ld_row4(emb, ic, lane);
    float4 chb = ld_row4(emb, id, lane);

    // ---- h, r, t gathers (overlap with the above) ----
    const int hidx = __ldg(hp + s);
    const int tidx = __ldg(tp + s);
    const float4 hv = ld_row4(emb, hidx, lane);
    const float4 tv = ld_row4(emb, tidx, lane);
    float4 rv;
    if (rp) {
        const int ridx = __ldg(rp + s);
        rv = __ldg(reinterpret_cast<const float4*>(rel + (size_t)ridx * D_DIM) + lane);
    } else {
        rv = __ldg(reinterpret_cast<const float4*>(rel) + lane);
    }

    float4 hr, rmt;
    hr.x = hv.x + rv.x;  hr.y = hv.y + rv.y;  hr.z = hv.z + rv.z;  hr.w = hv.w + rv.w;
    rmt.x = rv.x - tv.x; rmt.y = rv.y - tv.y; rmt.z = rv.z - tv.z; rmt.w = rv.w - tv.w;

    // ---- positive score (warp 0 only): GAMMA - sum |h + r - t| = |hr - t| ----
    if (warp == 0) {
        float p = fabsf(hr.x - tv.x) + fabsf(hr.y - tv.y)
                + fabsf(hr.z - tv.z) + fabsf(hr.w - tv.w);
        #pragma unroll
        for (int o = 16; o > 0; o >>= 1)
            p += __shfl_xor_sync(FULL, p, o);
        if (lane == 0) out_pos[s] = GAMMA - p;
    }

    float* onT = out_nt + (size_t)s * K_NEG;
    float* onH = out_nh + (size_t)s * K_NEG;

    // ---- Main loop: 8 iterations x (2 tail + 2 head) with 1-deep prefetch ----
    #pragma unroll
    for (int i = 0; i < 8; i++) {
        float4 nta, ntb, nha, nhb;
        if (i < 7) {
            const int a2 = __shfl_sync(FULL, myidx, 2 * i + 2);
            const int b2 = __shfl_sync(FULL, myidx, 2 * i + 3);
            const int c2 = __shfl_sync(FULL, myidx, 18 + 2 * i);
            const int d2 = __shfl_sync(FULL, myidx, 19 + 2 * i);
            nta = ld_row4(emb, a2, lane);
            ntb = ld_row4(emb, b2, lane);
            nha = ld_row4(emb, c2, lane);
            nhb = ld_row4(emb, d2, lane);
        }

        float sa = fabsf(hr.x - cta.x) + fabsf(hr.y - cta.y)
                 + fabsf(hr.z - cta.z) + fabsf(hr.w - cta.w);
        float sb = fabsf(hr.x - ctb.x) + fabsf(hr.y - ctb.y)
                 + fabsf(hr.z - ctb.z) + fabsf(hr.w - ctb.w);
        float sc = fabsf(cha.x + rmt.x) + fabsf(cha.y + rmt.y)
                 + fabsf(cha.z + rmt.z) + fabsf(cha.w + rmt.w);
        float sd = fabsf(chb.x + rmt.x) + fabsf(chb.y + rmt.y)
                 + fabsf(chb.z + rmt.z) + fabsf(chb.w + rmt.w);

        // 9-shuffle 4-value warp reduction:
        // after this, lane0=sa_tot, lane8=sc_tot, lane16=sb_tot, lane24=sd_tot
        sa += __shfl_xor_sync(FULL, sa, 16);
        sb += __shfl_xor_sync(FULL, sb, 16);
        sc += __shfl_xor_sync(FULL, sc, 16);
        sd += __shfl_xor_sync(FULL, sd, 16);
        float mab = (lane & 16) ? sb : sa;
        float mcd = (lane & 16) ? sd : sc;
        mab += __shfl_xor_sync(FULL, mab, 8);
        mcd += __shfl_xor_sync(FULL, mcd, 8);
        float m = (lane & 8) ? mcd : mab;
        m += __shfl_xor_sync(FULL, m, 4);
        m += __shfl_xor_sync(FULL, m, 2);
        m += __shfl_xor_sync(FULL, m, 1);

        const int j = j0 + 2 * i;
        const float val = GAMMA - m;
        if (lane == 0)       __stcs(onT + j,     val);
        else if (lane == 8)  __stcs(onH + j,     val);
        else if (lane == 16) __stcs(onT + j + 1, val);
        else if (lane == 24) __stcs(onH + j + 1, val);

        if (i < 7) { cta = nta; ctb = ntb; cha = nha; chb = nhb; }
    }
}

extern "C" void kernel_launch(void* const* d_in, const int* in_sizes, int n_in,
                              void* d_out, int out_size) {
    const float* emb   = (const float*)d_in[0];
    const float* relG2 = (const float*)d_in[1];
    const float* relTT = (const float*)d_in[2];
    const float* relTO = (const float*)d_in[3];
    const int* h1  = (const int*)d_in[4];
    const int* r1  = (const int*)d_in[5];
    const int* t1  = (const int*)d_in[6];
    const int* nt1 = (const int*)d_in[7];
    const int* nh1 = (const int*)d_in[8];
    const int* h2  = (const int*)d_in[9];
    const int* r2  = (const int*)d_in[10];
    const int* t2  = (const int*)d_in[11];
    const int* nt2 = (const int*)d_in[12];
    const int* nh2 = (const int*)d_in[13];
    const int* h3  = (const int*)d_in[14];
    const int* t3  = (const int*)d_in[15];
    const int* nt3 = (const int*)d_in[16];
    const int* nh3 = (const int*)d_in[17];

    dim3 grid(S_NUM, 3);
    sample_score_kernel<<<grid, 256>>>(
        emb, relG2, relTT, relTO,
        h1, r1, t1, nt1, nh1,
        h2, r2, t2, nt2, nh2,
        h3, t3, nt3, nh3,
        (float*)d_out);
}

// round 3
// speedup vs baseline: 1.1288x; 1.0319x over previous
#include <cuda_runtime.h>
#include <cstdint>

// Problem constants (match reference)
#define S_NUM 2048
#define K_NEG 128
#define D_DIM 128
#define GAMMA 12.0f

// Output layout: for each part p in {0,1,2}:
//   pos  [S]      at p*PART_STRIDE
//   neg_t[S*K]    at p*PART_STRIDE + S
//   neg_h[S*K]    at p*PART_STRIDE + S + S*K
#define PART_STRIDE (S_NUM + 2 * S_NUM * K_NEG)   // 526336

__device__ __forceinline__ uint32_t smem_u32(const void* p) {
    uint32_t a;
    asm("{ .reg .u64 t; cvta.to.shared.u64 t, %1; cvt.u32.u64 %0, t; }"
        : "=r"(a) : "l"(p));
    return a;
}

__device__ __forceinline__ void cp_async16(uint32_t saddr, const void* gaddr) {
    asm volatile("cp.async.cg.shared.global [%0], [%1], 16;"
                 :: "r"(saddr), "l"(gaddr));
}

__device__ __forceinline__ void cp_commit() {
    asm volatile("cp.async.commit_group;");
}

template <int N>
__device__ __forceinline__ void cp_wait() {
    asm volatile("cp.async.wait_group %0;" :: "n"(N));
}

__global__ __launch_bounds__(256, 5)
void sample_score_kernel(
    const float* __restrict__ emb,        // [N, D]
    const float* __restrict__ relG2,      // [R2, D]
    const float* __restrict__ relTT,      // [R1, D]
    const float* __restrict__ relTO,      // [D]
    const int* __restrict__ h1, const int* __restrict__ r1, const int* __restrict__ t1,
    const int* __restrict__ nt1, const int* __restrict__ nh1,
    const int* __restrict__ h2, const int* __restrict__ r2, const int* __restrict__ t2,
    const int* __restrict__ nt2, const int* __restrict__ nh2,
    const int* __restrict__ h3, const int* __restrict__ t3,
    const int* __restrict__ nt3, const int* __restrict__ nh3,
    float* __restrict__ out)
{
    // Staging: [warp][group][row][lane] 16B each -> 8*2*4*32*16 = 32 KB
    __shared__ float4 stage[8][2][4][32];

    const int s    = blockIdx.x;
    const int part = blockIdx.y;
    const int warp = threadIdx.x >> 5;
    const int lane = threadIdx.x & 31;

    // Select per-part pointers
    const int *hp, *tp, *ntp, *nhp;
    const int* rp;               // relation index array (nullptr for part 2)
    const float* rel;
    if (part == 0)      { hp=h1; rp=r1;      tp=t1; ntp=nt1; nhp=nh1; rel=relG2; }
    else if (part == 1) { hp=h2; rp=r2;      tp=t2; ntp=nt2; nhp=nh2; rel=relTT; }
    else                { hp=h3; rp=nullptr; tp=t3; ntp=nt3; nhp=nh3; rel=relTO; }

    const int j0 = warp * 16;    // this warp's 16 tail- and 16 head-negatives

    // Lane-parallel index load: lanes 0-15 carry nt indices, 16-31 carry nh indices.
    const int* nt_row = ntp + (size_t)s * K_NEG;
    const int* nh_row = nhp + (size_t)s * K_NEG;
    const int myidx = (lane < 16) ? __ldcs(nt_row + j0 + lane)
                                  : __ldcs(nh_row + j0 + (lane & 15));

    const unsigned FULL = 0xffffffffu;

    // smem base address for this lane's 16B chunk, row-stride = 512B, group-stride = 2KB
    const uint32_t sbase = smem_u32(&stage[warp][0][0][lane]);

    // Issue a 4-row group (iteration i) into group slot g. Rows:
    //   r0 = nt[2i], r1 = nt[2i+1], r2 = nh[2i], r3 = nh[2i+1]
    auto issue_group = [&](int i, int g) {
        const int a = __shfl_sync(FULL, myidx, 2 * i);
        const int b = __shfl_sync(FULL, myidx, 2 * i + 1);
        const int c = __shfl_sync(FULL, myidx, 16 + 2 * i);
        const int d = __shfl_sync(FULL, myidx, 17 + 2 * i);
        const uint32_t gb = sbase + g * 2048;
        cp_async16(gb,        emb + (size_t)a * D_DIM + lane * 4);
        cp_async16(gb + 512,  emb + (size_t)b * D_DIM + lane * 4);
        cp_async16(gb + 1024, emb + (size_t)c * D_DIM + lane * 4);
        cp_async16(gb + 1536, emb + (size_t)d * D_DIM + lane * 4);
        cp_commit();
    };

    // ---- Prologue: get the gather pipeline going before anything else ----
    issue_group(0, 0);
    issue_group(1, 1);

    // ---- h, r, t gathers (overlap with the staged groups) ----
    const int hidx = __ldg(hp + s);
    const int tidx = __ldg(tp + s);
    const float4 hv = __ldg(reinterpret_cast<const float4*>(emb + (size_t)hidx * D_DIM) + lane);
    const float4 tv = __ldg(reinterpret_cast<const float4*>(emb + (size_t)tidx * D_DIM) + lane);
    float4 rv;
    if (rp) {
        const int ridx = __ldg(rp + s);
        rv = __ldg(reinterpret_cast<const float4*>(rel + (size_t)ridx * D_DIM) + lane);
    } else {
        rv = __ldg(reinterpret_cast<const float4*>(rel) + lane);
    }

    float4 hr, rmt;
    hr.x = hv.x + rv.x;  hr.y = hv.y + rv.y;  hr.z = hv.z + rv.z;  hr.w = hv.w + rv.w;
    rmt.x = rv.x - tv.x; rmt.y = rv.y - tv.y; rmt.z = rv.z - tv.z; rmt.w = rv.w - tv.w;

    float* out_pos = out + (size_t)part * PART_STRIDE;
    float* onT = out_pos + S_NUM + (size_t)s * K_NEG;
    float* onH = onT + (size_t)S_NUM * K_NEG;

    // ---- positive score (warp 0 only): GAMMA - sum |h + r - t| = |hr - t| ----
    if (warp == 0) {
        float p = fabsf(hr.x - tv.x) + fabsf(hr.y - tv.y)
                + fabsf(hr.z - tv.z) + fabsf(hr.w - tv.w);
        #pragma unroll
        for (int o = 16; o > 0; o >>= 1)
            p += __shfl_xor_sync(FULL, p, o);
        if (lane == 0) out_pos[s] = GAMMA - p;
    }

    // ---- Main loop: 8 iterations, double-buffered smem staging ----
    #pragma unroll
    for (int i = 0; i < 8; i++) {
        if (i < 7) cp_wait<1>();   // oldest group complete
        else       cp_wait<0>();

        const int g = i & 1;
        // Each lane reads back exactly the 16B chunks it copied (no syncwarp needed).
        const float4 cta = stage[warp][g][0][lane];
        const float4 ctb = stage[warp][g][1][lane];
        const float4 cha = stage[warp][g][2][lane];
        const float4 chb = stage[warp][g][3][lane];

        float sa = fabsf(hr.x - cta.x) + fabsf(hr.y - cta.y)
                 + fabsf(hr.z - cta.z) + fabsf(hr.w - cta.w);
        float sb = fabsf(hr.x - ctb.x) + fabsf(hr.y - ctb.y)
                 + fabsf(hr.z - ctb.z) + fabsf(hr.w - ctb.w);
        float sc = fabsf(cha.x + rmt.x) + fabsf(cha.y + rmt.y)
                 + fabsf(cha.z + rmt.z) + fabsf(cha.w + rmt.w);
        float sd = fabsf(chb.x + rmt.x) + fabsf(chb.y + rmt.y)
                 + fabsf(chb.z + rmt.z) + fabsf(chb.w + rmt.w);

        // 9-shuffle 4-value warp reduction:
        // after this, lane0=sa_tot, lane8=sc_tot, lane16=sb_tot, lane24=sd_tot
        sa += __shfl_xor_sync(FULL, sa, 16);
        sb += __shfl_xor_sync(FULL, sb, 16);
        sc += __shfl_xor_sync(FULL, sc, 16);
        sd += __shfl_xor_sync(FULL, sd, 16);
        float mab = (lane & 16) ? sb : sa;
        float mcd = (lane & 16) ? sd : sc;
        mab += __shfl_xor_sync(FULL, mab, 8);
        mcd += __shfl_xor_sync(FULL, mcd, 8);
        float m = (lane & 8) ? mcd : mab;
        m += __shfl_xor_sync(FULL, m, 4);
        m += __shfl_xor_sync(FULL, m, 2);
        m += __shfl_xor_sync(FULL, m, 1);

        const int j = j0 + 2 * i;
        const float val = GAMMA - m;
        if (lane == 0)       __stcs(onT + j,     val);
        else if (lane == 8)  __stcs(onH + j,     val);
        else if (lane == 16) __stcs(onT + j + 1, val);
        else if (lane == 24) __stcs(onH + j + 1, val);

        // Refill the slot we just consumed. Issued AFTER the reduce consumed the
        // LDS results, so the loads from this slot are provably complete.
        if (i < 6) issue_group(i + 2, g);
    }
}

extern "C" void kernel_launch(void* const* d_in, const int* in_sizes, int n_in,
                              void* d_out, int out_size) {
    const float* emb   = (const float*)d_in[0];
    const float* relG2 = (const float*)d_in[1];
    const float* relTT = (const float*)d_in[2];
    const float* relTO = (const float*)d_in[3];
    const int* h1  = (const int*)d_in[4];
    const int* r1  = (const int*)d_in[5];
    const int* t1  = (const int*)d_in[6];
    const int* nt1 = (const int*)d_in[7];
    const int* nh1 = (const int*)d_in[8];
    const int* h2  = (const int*)d_in[9];
    const int* r2  = (const int*)d_in[10];
    const int* t2  = (const int*)d_in[11];
    const int* nt2 = (const int*)d_in[12];
    const int* nh2 = (const int*)d_in[13];
    const int* h3  = (const int*)d_in[14];
    const int* t3  = (const int*)d_in[15];
    const int* nt3 = (const int*)d_in[16];
    const int* nh3 = (const int*)d_in[17];

    dim3 grid(S_NUM, 3);
    sample_score_kernel<<<grid, 256>>>(
        emb, relG2, relTT, relTO,
        h1, r1, t1, nt1, nh1,
        h2, r2, t2, nt2, nh2,
        h3, t3, nt3, nh3,
        (float*)d_out);
}